// round 3
// baseline (speedup 1.0000x reference)
#include <cuda_runtime.h>
#include <cuda_bf16.h>

// MonotoneActivation: B=4096, G=512, K=4, D=8
// out[b,g,d] = sum_k coef_k * params[g, idx_k, d]
// where values of X[b,g,:] are sorted ascending (v0<=v1<=v2<=v3 with orig
// indices ind0..ind3), coef = [v0, v1-v0, v2-v1, v3-v2],
// idx_0 = 15, idx_{k+1} = idx_k - 2^{ind_k}.

#define B_DIM 4096
#define G_DIM 512
#define K_DIM 4
#define D_DIM 8

__global__ __launch_bounds__(256)
void monotone_act_kernel(const float* __restrict__ X,
                         const float* __restrict__ P,
                         float* __restrict__ out)
{
    int t = blockIdx.x * blockDim.x + threadIdx.x;   // t = b*G + g
    if (t >= B_DIM * G_DIM) return;
    int g = t & (G_DIM - 1);

    // ---- load 4 inputs as one float4 (coalesced, streaming) ----
    const float4* Xv = reinterpret_cast<const float4*>(X);
    float4 xv = __ldcs(&Xv[t]);

    float a0 = xv.x, a1 = xv.y, a2 = xv.z, a3 = xv.w;
    int   i0 = 0,    i1 = 1,    i2 = 2,    i3 = 3;

    // ---- 5-comparator sorting network (0,1)(2,3)(0,2)(1,3)(1,2) ----
    float tf; int ti;
#define CSWAP(x, y, ix, iy) \
    if (x > y) { tf = x; x = y; y = tf; ti = ix; ix = iy; iy = ti; }
    CSWAP(a0, a1, i0, i1)
    CSWAP(a2, a3, i2, i3)
    CSWAP(a0, a2, i0, i2)
    CSWAP(a1, a3, i1, i3)
    CSWAP(a1, a2, i1, i2)
#undef CSWAP

    // ---- coefficients ----
    float c0 = a0;
    float c1 = a1 - a0;
    float c2 = a2 - a1;
    float c3 = a3 - a2;

    // ---- gather indices: idx0 = 15, then subtract 2^ind ----
    int j0 = 15;
    int j1 = j0 - (1 << i0);
    int j2 = j1 - (1 << i1);
    int j3 = j2 - (1 << i2);

    // ---- gather 4 rows of 8 floats from params table for this g ----
    // P row stride = D_DIM floats; table stride = 16*D_DIM = 128 floats.
    const float4* pg = reinterpret_cast<const float4*>(P + (size_t)g * 16 * D_DIM);

    float4 r0a = __ldg(&pg[j0 * 2]);
    float4 r0b = __ldg(&pg[j0 * 2 + 1]);
    float4 r1a = __ldg(&pg[j1 * 2]);
    float4 r1b = __ldg(&pg[j1 * 2 + 1]);
    float4 r2a = __ldg(&pg[j2 * 2]);
    float4 r2b = __ldg(&pg[j2 * 2 + 1]);
    float4 r3a = __ldg(&pg[j3 * 2]);
    float4 r3b = __ldg(&pg[j3 * 2 + 1]);

    // ---- accumulate out = c0*r0 + c1*r1 + c2*r2 + c3*r3 ----
    float4 lo, hi;
    lo.x = fmaf(c3, r3a.x, fmaf(c2, r2a.x, fmaf(c1, r1a.x, c0 * r0a.x)));
    lo.y = fmaf(c3, r3a.y, fmaf(c2, r2a.y, fmaf(c1, r1a.y, c0 * r0a.y)));
    lo.z = fmaf(c3, r3a.z, fmaf(c2, r2a.z, fmaf(c1, r1a.z, c0 * r0a.z)));
    lo.w = fmaf(c3, r3a.w, fmaf(c2, r2a.w, fmaf(c1, r1a.w, c0 * r0a.w)));
    hi.x = fmaf(c3, r3b.x, fmaf(c2, r2b.x, fmaf(c1, r1b.x, c0 * r0b.x)));
    hi.y = fmaf(c3, r3b.y, fmaf(c2, r2b.y, fmaf(c1, r1b.y, c0 * r0b.y)));
    hi.z = fmaf(c3, r3b.z, fmaf(c2, r2b.z, fmaf(c1, r1b.z, c0 * r0b.z)));
    hi.w = fmaf(c3, r3b.w, fmaf(c2, r2b.w, fmaf(c1, r1b.w, c0 * r0b.w)));

    // ---- write 8 floats = 2 float4 (coalesced, streaming) ----
    float4* Ov = reinterpret_cast<float4*>(out);
    __stcs(&Ov[t * 2],     lo);
    __stcs(&Ov[t * 2 + 1], hi);
}

extern "C" void kernel_launch(void* const* d_in, const int* in_sizes, int n_in,
                              void* d_out, int out_size)
{
    const float* X = (const float*)d_in[0];   // (4096, 2048) f32
    const float* P = (const float*)d_in[1];   // (512, 16, 8) f32
    float* out     = (float*)d_out;           // (4096, 4096) f32

    const int total = B_DIM * G_DIM;          // 2,097,152 threads
    const int block = 256;
    const int grid  = (total + block - 1) / block;
    monotone_act_kernel<<<grid, block>>>(X, P, out);
}

// round 4
// speedup vs baseline: 1.7914x; 1.7914x over previous
#include <cuda_runtime.h>
#include <cuda_bf16.h>

// MonotoneActivation: B=4096, G=512, K=4, D=8
// out[b,g,d] = sum_k coef_k * params[g, idx_k, d]
// Sorted ascending v0<=v1<=v2<=v3 with original indices ind0..ind3,
// coef = [v0, v1-v0, v2-v1, v3-v2], idx_0 = 15, idx_{k+1} = idx_k - 2^{ind_k}.
//
// R3 lesson: per-lane-distinct-g gathers cost up to 32 L1tex wavefronts per
// LDG -> L1 bound at 87.9%. This version stages the 64 param tables a block
// needs into padded shared memory (stride 132 floats -> conflict-tiled
// LDS.128) and gathers from smem instead.

#define B_DIM 4096
#define G_DIM 512
#define TG 64            // g-tables per block
#define TB 32            // b-rows per block
#define THREADS 256
#define PSTRIDE 132      // padded floats per table (128 data + 4 pad)

__global__ __launch_bounds__(THREADS)
void monotone_act_kernel(const float* __restrict__ X,
                         const float* __restrict__ P,
                         float* __restrict__ out)
{
    __shared__ float sP[TG * PSTRIDE];           // 33792 B

    const int g0 = blockIdx.x * TG;
    const int b0 = blockIdx.y * TB;

    // ---- stage TG param tables (TG*128 floats) into padded smem ----
    // gmem is contiguous: P + g0*128 ... float4 index i covers table i>>5, quad i&31
    const float4* Pv = reinterpret_cast<const float4*>(P + (size_t)g0 * 128);
    #pragma unroll
    for (int i = threadIdx.x; i < TG * 32; i += THREADS) {
        int gt = i >> 5;
        int w4 = i & 31;
        float4 v = __ldg(&Pv[i]);
        *reinterpret_cast<float4*>(&sP[gt * PSTRIDE + w4 * 4]) = v;
    }
    __syncthreads();

    const int gl = threadIdx.x & (TG - 1);       // 0..63  (consecutive g in warp)
    const int bl = threadIdx.x >> 6;             // 0..3
    // table base: gl*132 floats = gl*528 bytes, 16B-aligned -> float4 ok
    const float4* tab = reinterpret_cast<const float4*>(&sP[gl * PSTRIDE]);

    const float4* Xv = reinterpret_cast<const float4*>(X);
    float4*       Ov = reinterpret_cast<float4*>(out);

    #pragma unroll
    for (int it = 0; it < TB / 4; ++it) {
        const int b = b0 + it * 4 + bl;
        const int t = (b << 9) + g0 + gl;        // b*G + g

        float4 xv = __ldcs(&Xv[t]);

        float a0 = xv.x, a1 = xv.y, a2 = xv.z, a3 = xv.w;
        int   i0 = 0,    i1 = 1,    i2 = 2,    i3 = 3;

        // 5-comparator sorting network (0,1)(2,3)(0,2)(1,3)(1,2)
        float tf; int ti;
#define CSWAP(x, y, ix, iy) \
        if (x > y) { tf = x; x = y; y = tf; ti = ix; ix = iy; iy = ti; }
        CSWAP(a0, a1, i0, i1)
        CSWAP(a2, a3, i2, i3)
        CSWAP(a0, a2, i0, i2)
        CSWAP(a1, a3, i1, i3)
        CSWAP(a1, a2, i1, i2)
#undef CSWAP

        float c0 = a0;
        float c1 = a1 - a0;
        float c2 = a2 - a1;
        float c3 = a3 - a2;

        int j0 = 15;
        int j1 = j0 - (1 << i0);
        int j2 = j1 - (1 << i1);
        int j3 = j2 - (1 << i2);

        // gathers from smem (row j -> float4 index j*2, j*2+1)
        float4 r0a = tab[j0 * 2];
        float4 r0b = tab[j0 * 2 + 1];
        float4 r1a = tab[j1 * 2];
        float4 r1b = tab[j1 * 2 + 1];
        float4 r2a = tab[j2 * 2];
        float4 r2b = tab[j2 * 2 + 1];
        float4 r3a = tab[j3 * 2];
        float4 r3b = tab[j3 * 2 + 1];

        float4 lo, hi;
        lo.x = fmaf(c3, r3a.x, fmaf(c2, r2a.x, fmaf(c1, r1a.x, c0 * r0a.x)));
        lo.y = fmaf(c3, r3a.y, fmaf(c2, r2a.y, fmaf(c1, r1a.y, c0 * r0a.y)));
        lo.z = fmaf(c3, r3a.z, fmaf(c2, r2a.z, fmaf(c1, r1a.z, c0 * r0a.z)));
        lo.w = fmaf(c3, r3a.w, fmaf(c2, r2a.w, fmaf(c1, r1a.w, c0 * r0a.w)));
        hi.x = fmaf(c3, r3b.x, fmaf(c2, r2b.x, fmaf(c1, r1b.x, c0 * r0b.x)));
        hi.y = fmaf(c3, r3b.y, fmaf(c2, r2b.y, fmaf(c1, r1b.y, c0 * r0b.y)));
        hi.z = fmaf(c3, r3b.z, fmaf(c2, r2b.z, fmaf(c1, r1b.z, c0 * r0b.z)));
        hi.w = fmaf(c3, r3b.w, fmaf(c2, r2b.w, fmaf(c1, r1b.w, c0 * r0b.w)));

        __stcs(&Ov[t * 2],     lo);
        __stcs(&Ov[t * 2 + 1], hi);
    }
}

extern "C" void kernel_launch(void* const* d_in, const int* in_sizes, int n_in,
                              void* d_out, int out_size)
{
    const float* X = (const float*)d_in[0];   // (4096, 2048) f32
    const float* P = (const float*)d_in[1];   // (512, 16, 8)  f32
    float* out     = (float*)d_out;           // (4096, 4096) f32

    dim3 grid(G_DIM / TG, B_DIM / TB);        // (8, 128) = 1024 blocks
    monotone_act_kernel<<<grid, THREADS>>>(X, P, out);
}

// round 5
// speedup vs baseline: 1.9485x; 1.0877x over previous
#include <cuda_runtime.h>
#include <cuda_bf16.h>

// MonotoneActivation: B=4096, G=512, K=4, D=8
// out[b,g,d] = sum_k coef_k * params[g, idx_k, d]
// Sorted ascending v0<=v1<=v2<=v3 with orig indices ind0..ind3,
// coef = [v0, v1-v0, v2-v1, v3-v2], idx_0 = 15 (ALWAYS), idx_{k+1} = idx_k - 2^{ind_k}.
//
// R4 lessons: L1tex still top (67%) at issue=22.7% -> latency-bound on LDS
// chains, and 2 of the 8 gather LDS are loop-invariant (row 15).
// This round: hoist row15 to registers, 4-wide software pipeline per thread,
// allow 64 regs for MLP.

#define B_DIM 4096
#define G_DIM 512
#define TG 64            // g-tables per block
#define TB 32            // b-rows per block
#define THREADS 256
#define PSTRIDE 132      // padded floats per table (128 data + 4 pad)

__global__ __launch_bounds__(THREADS, 4)
void monotone_act_kernel(const float* __restrict__ X,
                         const float* __restrict__ P,
                         float* __restrict__ out)
{
    __shared__ float sP[TG * PSTRIDE];           // 33792 B

    const int g0 = blockIdx.x * TG;
    const int b0 = blockIdx.y * TB;

    // ---- stage TG param tables (TG*128 floats) into padded smem ----
    const float4* Pv = reinterpret_cast<const float4*>(P + (size_t)g0 * 128);
    #pragma unroll
    for (int i = threadIdx.x; i < TG * 32; i += THREADS) {
        int gt = i >> 5;
        int w4 = i & 31;
        float4 v = __ldg(&Pv[i]);
        *reinterpret_cast<float4*>(&sP[gt * PSTRIDE + w4 * 4]) = v;
    }
    __syncthreads();

    const int gl = threadIdx.x & (TG - 1);       // 0..63 (consecutive g in warp)
    const int bl = threadIdx.x >> 6;             // 0..3
    const float4* tab = reinterpret_cast<const float4*>(&sP[gl * PSTRIDE]);

    // row 15 is gathered by EVERY pair (j0 == 15 always) -> keep in registers
    const float4 r15a = tab[30];
    const float4 r15b = tab[31];

    const float4* Xv = reinterpret_cast<const float4*>(X);
    float4*       Ov = reinterpret_cast<float4*>(out);

    #pragma unroll
    for (int half = 0; half < 2; ++half) {
        // ---- preload 4 independent X vectors (deep MLP) ----
        int tbase[4];
        float4 xv[4];
        #pragma unroll
        for (int u = 0; u < 4; ++u) {
            const int b = b0 + half * 16 + u * 4 + bl;
            tbase[u] = (b << 9) + g0 + gl;       // b*G + g
            xv[u] = __ldcs(&Xv[tbase[u]]);
        }

        #pragma unroll
        for (int u = 0; u < 4; ++u) {
            float a0 = xv[u].x, a1 = xv[u].y, a2 = xv[u].z, a3 = xv[u].w;
            int   i0 = 0,       i1 = 1,       i2 = 2,       i3 = 3;

            // 5-comparator sorting network (0,1)(2,3)(0,2)(1,3)(1,2)
            float tf; int ti;
#define CSWAP(x, y, ix, iy) \
            if (x > y) { tf = x; x = y; y = tf; ti = ix; ix = iy; iy = ti; }
            CSWAP(a0, a1, i0, i1)
            CSWAP(a2, a3, i2, i3)
            CSWAP(a0, a2, i0, i2)
            CSWAP(a1, a3, i1, i3)
            CSWAP(a1, a2, i1, i2)
#undef CSWAP

            float c0 = a0;
            float c1 = a1 - a0;
            float c2 = a2 - a1;
            float c3 = a3 - a2;

            int j1 = 15 - (1 << i0);
            int j2 = j1 - (1 << i1);
            int j3 = j2 - (1 << i2);

            // gathers from smem (row j -> float4 index j*2, j*2+1); row15 in regs
            float4 r1a = tab[j1 * 2];
            float4 r1b = tab[j1 * 2 + 1];
            float4 r2a = tab[j2 * 2];
            float4 r2b = tab[j2 * 2 + 1];
            float4 r3a = tab[j3 * 2];
            float4 r3b = tab[j3 * 2 + 1];

            float4 lo, hi;
            lo.x = fmaf(c3, r3a.x, fmaf(c2, r2a.x, fmaf(c1, r1a.x, c0 * r15a.x)));
            lo.y = fmaf(c3, r3a.y, fmaf(c2, r2a.y, fmaf(c1, r1a.y, c0 * r15a.y)));
            lo.z = fmaf(c3, r3a.z, fmaf(c2, r2a.z, fmaf(c1, r1a.z, c0 * r15a.z)));
            lo.w = fmaf(c3, r3a.w, fmaf(c2, r2a.w, fmaf(c1, r1a.w, c0 * r15a.w)));
            hi.x = fmaf(c3, r3b.x, fmaf(c2, r2b.x, fmaf(c1, r1b.x, c0 * r15b.x)));
            hi.y = fmaf(c3, r3b.y, fmaf(c2, r2b.y, fmaf(c1, r1b.y, c0 * r15b.y)));
            hi.z = fmaf(c3, r3b.z, fmaf(c2, r2b.z, fmaf(c1, r1b.z, c0 * r15b.z)));
            hi.w = fmaf(c3, r3b.w, fmaf(c2, r2b.w, fmaf(c1, r1b.w, c0 * r15b.w)));

            __stcs(&Ov[tbase[u] * 2],     lo);
            __stcs(&Ov[tbase[u] * 2 + 1], hi);
        }
    }
}

extern "C" void kernel_launch(void* const* d_in, const int* in_sizes, int n_in,
                              void* d_out, int out_size)
{
    const float* X = (const float*)d_in[0];   // (4096, 2048) f32
    const float* P = (const float*)d_in[1];   // (512, 16, 8)  f32
    float* out     = (float*)d_out;           // (4096, 4096) f32

    dim3 grid(G_DIM / TG, B_DIM / TB);        // (8, 128) = 1024 blocks
    monotone_act_kernel<<<grid, THREADS>>>(X, P, out);
}